// round 9
// baseline (speedup 1.0000x reference)
#include <cuda_runtime.h>
#include <math.h>

#define B_  8
#define L_  4096
#define H_  16
#define DE  1024
#define NCHUNK 32
#define LCHUNK 128

// Scratch (static device globals — allowed; no runtime allocation)
__device__ float g_Spart[B_ * NCHUNK * H_ * DE];   // 16 MB partial S
__device__ float g_ktv[B_ * DE];                   // [b][h*64+d]
__device__ float g_V1[B_ * H_];                    // sum_l v
__device__ float g_c[B_ * H_];                     // bq_h . ktv
__device__ float g_G[B_ * H_ * DE];                // [b][h][e]

typedef unsigned long long u64;

__device__ __forceinline__ void ffma2(u64 &d, u64 a, u64 b) {
    asm("fma.rn.f32x2 %0, %1, %2, %0;" : "+l"(d) : "l"(a), "l"(b));
}
__device__ __forceinline__ u64 pack2(float lo, float hi) {
    union { u64 u; float2 f; } c; c.f.x = lo; c.f.y = hi; return c.u;
}
__device__ __forceinline__ float2 unpack2(u64 v) {
    union { u64 u; float2 f; } c; c.u = v; return c.f;
}

// ---------------------------------------------------------------- K0: zero
__global__ void k_zero() {
    int t = blockIdx.x * blockDim.x + threadIdx.x;
    if (t < B_ * DE) g_ktv[t] = 0.f;
    if (t < B_ * H_) g_V1[t] = 0.f;
}

// --------------------------------------------------- KA: fused v + S-partials
// grid = B*NCHUNK (256), 256 threads.
// smem: WvT [16][1026] (padded, conflict-free) + v_s [16][64]
__global__ void __launch_bounds__(256, 2)
k_vS(const float* __restrict__ x, const float* __restrict__ Wv,
     const float* __restrict__ bv) {
    extern __shared__ float sh[];
    float* wvT = sh;                 // 16*1026 floats
    float* v_s = sh + 16 * 1026;     // 16*64 floats

    const int b     = blockIdx.x >> 5;
    const int chunk = blockIdx.x & 31;
    const int l0    = chunk * LCHUNK;
    const int tid   = threadIdx.x;

    // Load Wv transposed into smem: wvT[h][e] = Wv[e*16+h]
    for (int idx = tid; idx < DE * H_; idx += 256) {
        int e = idx >> 4, h = idx & 15;
        wvT[h * 1026 + e] = Wv[idx];
    }
    __syncthreads();

    const int h  = tid & 15;
    const int lg = tid >> 4;
    const float bvh = bv[h];

    // Phase-B accumulators: this thread owns e columns [tid*4, tid*4+4)
    // for ALL 16 heads, accumulated over all 128 rows of the chunk.
    u64 accS[16][2];
#pragma unroll
    for (int i = 0; i < 16; i++) { accS[i][0] = 0ULL; accS[i][1] = 0ULL; }
    const int e0 = tid * 4;
    float vsum = 0.f;

    for (int half = 0; half < 2; half++) {
        // ---- Phase A: v for 64 rows (thread: head h, rows lg*4..lg*4+3)
        {
            const int rbase = l0 + half * 64 + lg * 4;
            const u64* xr0 = (const u64*)(x + ((size_t)b * L_ + rbase + 0) * DE);
            const u64* xr1 = (const u64*)(x + ((size_t)b * L_ + rbase + 1) * DE);
            const u64* xr2 = (const u64*)(x + ((size_t)b * L_ + rbase + 2) * DE);
            const u64* xr3 = (const u64*)(x + ((size_t)b * L_ + rbase + 3) * DE);
            const u64* wp  = (const u64*)(wvT + h * 1026);
            u64 a0 = 0, a1 = 0, a2 = 0, a3 = 0;
#pragma unroll 4
            for (int e2 = 0; e2 < DE / 2; e2++) {
                u64 w2 = wp[e2];
                ffma2(a0, xr0[e2], w2);
                ffma2(a1, xr1[e2], w2);
                ffma2(a2, xr2[e2], w2);
                ffma2(a3, xr3[e2], w2);
            }
            float2 f0 = unpack2(a0), f1 = unpack2(a1);
            float2 f2 = unpack2(a2), f3 = unpack2(a3);
            float v0 = f0.x + f0.y + bvh;
            float v1 = f1.x + f1.y + bvh;
            float v2 = f2.x + f2.y + bvh;
            float v3 = f3.x + f3.y + bvh;
            v_s[h * 64 + lg * 4 + 0] = v0;
            v_s[h * 64 + lg * 4 + 1] = v1;
            v_s[h * 64 + lg * 4 + 2] = v2;
            v_s[h * 64 + lg * 4 + 3] = v3;
            vsum += v0 + v1 + v2 + v3;
        }
        __syncthreads();

        // ---- Phase B: S[h][e0..e0+3] += x[l][e]*v[h][l] over these 64 rows
        {
            // Row stride of x in ulonglong2 (16 B = 4 floats) units is DE/4.
            const ulonglong2* xp =
                (const ulonglong2*)(x + ((size_t)b * L_ + l0 + half * 64) * DE + e0);
            for (int l = 0; l < 64; l++) {
                ulonglong2 x4 = xp[(size_t)l * (DE / 4)];
#pragma unroll
                for (int hh = 0; hh < 16; hh++) {
                    float v = v_s[hh * 64 + l];     // smem broadcast
                    u64 vv = pack2(v, v);
                    ffma2(accS[hh][0], x4.x, vv);
                    ffma2(accS[hh][1], x4.y, vv);
                }
            }
        }
        __syncthreads();   // protect v_s before next half overwrites it
    }

    // V1 reduction: lane L and L^16 share h
    vsum += __shfl_xor_sync(0xffffffffu, vsum, 16);
    if ((tid & 31) < 16) atomicAdd(&g_V1[b * 16 + h], vsum);

    // Store S partials (float4 per head)
    float* sp = &g_Spart[((size_t)b * NCHUNK + chunk) * H_ * DE];
#pragma unroll
    for (int hh = 0; hh < 16; hh++) {
        float2 lo = unpack2(accS[hh][0]);
        float2 hi = unpack2(accS[hh][1]);
        float4 o = make_float4(lo.x, lo.y, hi.x, hi.y);
        *(float4*)&sp[hh * DE + e0] = o;
    }
}

// ------------------------------------------------ KC: reduce S, compute ktv
// grid 32: (b, e-segment of 256), 1024 threads; thread t -> hd = t
__global__ void __launch_bounds__(1024)
k_ktv(const float* __restrict__ Wk, const float* __restrict__ bk) {
    __shared__ float S_s[16 * 257];   // padded
    const int b   = blockIdx.x >> 2;
    const int seg = blockIdx.x & 3;
    const int t   = threadIdx.x;
    const int h   = t >> 6;
    const int ei  = (t & 63) * 4;

    float4 a4 = make_float4(0.f, 0.f, 0.f, 0.f);
    for (int ch = 0; ch < NCHUNK; ch++) {
        const float4 p = *(const float4*)
            &g_Spart[(((size_t)b * NCHUNK + ch) * H_ + h) * DE + seg * 256 + ei];
        a4.x += p.x; a4.y += p.y; a4.z += p.z; a4.w += p.w;
    }
    S_s[h * 257 + ei + 0] = a4.x;
    S_s[h * 257 + ei + 1] = a4.y;
    S_s[h * 257 + ei + 2] = a4.z;
    S_s[h * 257 + ei + 3] = a4.w;
    __syncthreads();

    float acc = 0.f;
    const float* wkp = Wk + (size_t)seg * 256 * DE + t;   // coalesced across t
    const float* ss  = &S_s[h * 257];
#pragma unroll 4
    for (int e = 0; e < 256; e++)
        acc += wkp[(size_t)e * DE] * ss[e];
    if (seg == 0) acc += bk[t] * g_V1[b * 16 + h];
    atomicAdd(&g_ktv[b * DE + t], acc);
}

// ------------------------------------------------------- KD: g and c
// grid 32: (b, e-quarter), 256 threads; thread owns one e row of Wq
__global__ void __launch_bounds__(256)
k_g(const float* __restrict__ Wq, const float* __restrict__ bq) {
    __shared__ float ktv_s[DE];
    const int b  = blockIdx.x >> 2;
    const int eq = blockIdx.x & 3;
    const int t  = threadIdx.x;
    for (int i = t; i < DE; i += 256) ktv_s[i] = g_ktv[b * DE + i];
    __syncthreads();

    const int e = eq * 256 + t;
    const float4* wq = (const float4*)(Wq + (size_t)e * DE);  // per-thread row stream
    float acc[16];
#pragma unroll
    for (int hh = 0; hh < 16; hh++) {
        float a = 0.f;
#pragma unroll 4
        for (int j = 0; j < 16; j++) {
            int q4 = hh * 16 + j;
            float4 w = wq[q4];
            const float* kt = &ktv_s[q4 * 4];
            a += w.x * kt[0] + w.y * kt[1] + w.z * kt[2] + w.w * kt[3];
        }
        acc[hh] = a;
    }
#pragma unroll
    for (int hh = 0; hh < 16; hh++)
        g_G[((size_t)b * H_ + hh) * DE + e] = acc[hh];

    if (eq == 0 && t < 16) {
        float c = 0.f;
        for (int d = 0; d < 64; d++) c += bq[t * 64 + d] * ktv_s[t * 64 + d];
        g_c[b * 16 + t] = c;
    }
}

// --------------------------------------------- KE: z = (x.g + c)/8 -> sigmoid
// grid = B*64 (512), 256 threads; thread: (head h, 4 rows)
// mask is int32 (bool passed as int32 by the harness — verified by the
// sqrt(0.75) rel_err signature in round 8).
__global__ void __launch_bounds__(256)
k_out(const float* __restrict__ x, const int* __restrict__ mask,
      float* __restrict__ out) {
    extern __shared__ float sh[];
    float* gs  = sh;              // [16][1026]
    float* c_s = sh + 16 * 1026;  // [16]

    const int b   = blockIdx.x >> 6;
    const int lt  = blockIdx.x & 63;
    const int l0  = lt * 64;
    const int tid = threadIdx.x;

    for (int idx = tid; idx < H_ * DE; idx += 256) {
        int hh = idx >> 10, e = idx & 1023;
        gs[hh * 1026 + e] = g_G[(size_t)b * H_ * DE + idx];
    }
    if (tid < 16) c_s[tid] = g_c[b * 16 + tid];
    __syncthreads();

    const int h  = tid & 15;
    const int lg = tid >> 4;
    const int rbase = l0 + lg * 4;
    const u64* xr0 = (const u64*)(x + ((size_t)b * L_ + rbase + 0) * DE);
    const u64* xr1 = (const u64*)(x + ((size_t)b * L_ + rbase + 1) * DE);
    const u64* xr2 = (const u64*)(x + ((size_t)b * L_ + rbase + 2) * DE);
    const u64* xr3 = (const u64*)(x + ((size_t)b * L_ + rbase + 3) * DE);
    const u64* wp  = (const u64*)(gs + h * 1026);

    u64 a[4] = {0ULL, 0ULL, 0ULL, 0ULL};
#pragma unroll 4
    for (int e2 = 0; e2 < DE / 2; e2++) {
        u64 w2 = wp[e2];
        ffma2(a[0], xr0[e2], w2);
        ffma2(a[1], xr1[e2], w2);
        ffma2(a[2], xr2[e2], w2);
        ffma2(a[3], xr3[e2], w2);
    }
    const float ch = c_s[h];
#pragma unroll
    for (int j = 0; j < 4; j++) {
        float2 f = unpack2(a[j]);
        float z = (f.x + f.y + ch) * 0.125f;
        float p = 1.f / (1.f + expf(-z));
        int l = rbase + j;
        out[((size_t)b * H_ + h) * L_ + l] = (mask[b * L_ + l] != 0) ? p : 0.f;
    }
}

// --------------------------------------------------------------- launch
extern "C" void kernel_launch(void* const* d_in, const int* in_sizes, int n_in,
                              void* d_out, int out_size) {
    const float* x  = (const float*)d_in[0];
    const int*   mk = (const int*)d_in[1];     // bool mask delivered as int32
    const float* Wq = (const float*)d_in[2];
    const float* bq = (const float*)d_in[3];
    const float* Wk = (const float*)d_in[4];
    const float* bk = (const float*)d_in[5];
    const float* Wv = (const float*)d_in[6];
    const float* bv = (const float*)d_in[7];
    float* out      = (float*)d_out;

    const int smemA = (16 * 1026 + 16 * 64) * 4;   // 69760 B
    const int smemE = (16 * 1026 + 16) * 4;        // 65728 B
    cudaFuncSetAttribute(k_vS,  cudaFuncAttributeMaxDynamicSharedMemorySize, smemA);
    cudaFuncSetAttribute(k_out, cudaFuncAttributeMaxDynamicSharedMemorySize, smemE);

    k_zero<<<32, 256>>>();
    k_vS  <<<B_ * NCHUNK, 256, smemA>>>(x, Wv, bv);
    k_ktv <<<32, 1024>>>(Wk, bk);
    k_g   <<<32, 256>>>(Wq, bq);
    k_out <<<B_ * 64, 256, smemE>>>(x, mk, out);
}

// round 10
// speedup vs baseline: 1.2567x; 1.2567x over previous
#include <cuda_runtime.h>
#include <math.h>

#define B_  8
#define L_  4096
#define H_  16
#define DE  1024
#define NCHUNK 32
#define LCHUNK 128

// Scratch (static device globals — allowed; no runtime allocation)
__device__ float g_S[B_ * H_ * DE];     // reduced S [b][h][e] (atomic-accumulated)
__device__ float g_ktv[B_ * DE];        // [b][h*64+d]
__device__ float g_V1[B_ * H_];         // sum_l v
__device__ float g_c[B_ * H_];          // bq_h . ktv
__device__ float g_G[B_ * H_ * DE];     // [b][h][e]

typedef unsigned long long u64;

__device__ __forceinline__ void ffma2(u64 &d, u64 a, u64 b) {
    asm("fma.rn.f32x2 %0, %1, %2, %0;" : "+l"(d) : "l"(a), "l"(b));
}
__device__ __forceinline__ u64 pack2(float lo, float hi) {
    union { u64 u; float2 f; } c; c.f.x = lo; c.f.y = hi; return c.u;
}
__device__ __forceinline__ float2 unpack2(u64 v) {
    union { u64 u; float2 f; } c; c.u = v; return c.f;
}

// ---------------------------------------------------------------- K0: zero
__global__ void k_zero() {
    int t = blockIdx.x * blockDim.x + threadIdx.x;   // 512*256 = 131072 = B*H*DE
    g_S[t] = 0.f;
    if (t < B_ * H_) g_V1[t] = 0.f;
}

// --------------------------------------------------- KA: fused v + S
// grid = B*NCHUNK (256), 256 threads.
// smem: WvT [16][1026] floats (conflict-free) + v_s2 [16][64] u64 (packed v,v)
__global__ void __launch_bounds__(256, 2)
k_vS(const float* __restrict__ x, const float* __restrict__ Wv,
     const float* __restrict__ bv) {
    extern __shared__ float sh[];
    float* wvT = sh;                       // 16*1026 floats
    u64*   v_s2 = (u64*)(sh + 16 * 1026);  // 16*64 u64

    const int b     = blockIdx.x >> 5;
    const int chunk = blockIdx.x & 31;
    const int l0    = chunk * LCHUNK;
    const int tid   = threadIdx.x;

    // Load Wv transposed: wvT[h][e] = Wv[e*16+h]
    for (int idx = tid; idx < DE * H_; idx += 256) {
        int e = idx >> 4, h = idx & 15;
        wvT[h * 1026 + e] = Wv[idx];
    }
    __syncthreads();

    const int h  = tid & 15;
    const int lg = tid >> 4;
    const float bvh = bv[h];

    u64 accS[16][2];
#pragma unroll
    for (int i = 0; i < 16; i++) { accS[i][0] = 0ULL; accS[i][1] = 0ULL; }
    const int e0 = tid * 4;
    float vsum = 0.f;

    for (int half = 0; half < 2; half++) {
        // ---- Phase A: v for 64 rows (thread: head h, rows lg*4..lg*4+3)
        {
            const int rbase = l0 + half * 64 + lg * 4;
            const ulonglong2* xr0 = (const ulonglong2*)(x + ((size_t)b * L_ + rbase + 0) * DE);
            const ulonglong2* xr1 = (const ulonglong2*)(x + ((size_t)b * L_ + rbase + 1) * DE);
            const ulonglong2* xr2 = (const ulonglong2*)(x + ((size_t)b * L_ + rbase + 2) * DE);
            const ulonglong2* xr3 = (const ulonglong2*)(x + ((size_t)b * L_ + rbase + 3) * DE);
            const u64* wp = (const u64*)(wvT + h * 1026);
            u64 a0 = 0, a1 = 0, a2 = 0, a3 = 0;
#pragma unroll 4
            for (int e4 = 0; e4 < DE / 4; e4++) {
                u64 w0 = wp[2 * e4], w1 = wp[2 * e4 + 1];
                ulonglong2 p0 = xr0[e4], p1 = xr1[e4], p2 = xr2[e4], p3 = xr3[e4];
                ffma2(a0, p0.x, w0); ffma2(a0, p0.y, w1);
                ffma2(a1, p1.x, w0); ffma2(a1, p1.y, w1);
                ffma2(a2, p2.x, w0); ffma2(a2, p2.y, w1);
                ffma2(a3, p3.x, w0); ffma2(a3, p3.y, w1);
            }
            float2 f0 = unpack2(a0), f1 = unpack2(a1);
            float2 f2 = unpack2(a2), f3 = unpack2(a3);
            float v0 = f0.x + f0.y + bvh;
            float v1 = f1.x + f1.y + bvh;
            float v2 = f2.x + f2.y + bvh;
            float v3 = f3.x + f3.y + bvh;
            v_s2[h * 64 + lg * 4 + 0] = pack2(v0, v0);
            v_s2[h * 64 + lg * 4 + 1] = pack2(v1, v1);
            v_s2[h * 64 + lg * 4 + 2] = pack2(v2, v2);
            v_s2[h * 64 + lg * 4 + 3] = pack2(v3, v3);
            vsum += v0 + v1 + v2 + v3;
        }
        __syncthreads();

        // ---- Phase B: S[h][e0..e0+3] += x[l][e]*v[h][l], software-pipelined x
        {
            const ulonglong2* xp =
                (const ulonglong2*)(x + ((size_t)b * L_ + l0 + half * 64) * DE + e0);
            ulonglong2 x4 = xp[0];
            for (int l = 0; l < 64; l++) {
                ulonglong2 nxt = xp[(size_t)(l + 1 < 64 ? l + 1 : l) * (DE / 4)];
#pragma unroll
                for (int hh = 0; hh < 16; hh++) {
                    u64 v2 = v_s2[hh * 64 + l];    // smem broadcast, pre-packed
                    ffma2(accS[hh][0], x4.x, v2);
                    ffma2(accS[hh][1], x4.y, v2);
                }
                x4 = nxt;
            }
        }
        __syncthreads();   // protect v_s2 before next half overwrites it
    }

    // V1 reduction: lane L and L^16 share h
    vsum += __shfl_xor_sync(0xffffffffu, vsum, 16);
    if ((tid & 31) < 16) atomicAdd(&g_V1[b * 16 + h], vsum);

    // Accumulate S directly (distinct addresses within a block; 32 blocks/b contend)
    float* sp = g_S + (size_t)b * H_ * DE;
#pragma unroll
    for (int hh = 0; hh < 16; hh++) {
        float2 lo = unpack2(accS[hh][0]);
        float2 hi = unpack2(accS[hh][1]);
        atomicAdd(sp + hh * DE + e0 + 0, lo.x);
        atomicAdd(sp + hh * DE + e0 + 1, lo.y);
        atomicAdd(sp + hh * DE + e0 + 2, hi.x);
        atomicAdd(sp + hh * DE + e0 + 3, hi.y);
    }
}

// ------------------------------------------------ KC: ktv = Wk^T S + bk*V1
// grid 64 = 8b x 8seg, 1024 threads. Each block produces 128 outputs (tg),
// 8-way split over e with smem reduction.
__global__ void __launch_bounds__(1024)
k_ktv(const float* __restrict__ Wk, const float* __restrict__ bk) {
    __shared__ float S2[2 * 1024];
    __shared__ float part[1024];
    const int b   = blockIdx.x >> 3;
    const int seg = blockIdx.x & 7;
    const int t   = threadIdx.x;

    for (int i = t; i < 2048; i += 1024)
        S2[i] = g_S[((size_t)b * 16 + seg * 2) * 1024 + i];
    __syncthreads();

    const int ec = t >> 7;            // e-chunk 0..7
    const int tl = t & 127;           // local output
    const int tg = seg * 128 + tl;    // global hd index
    const int hl = tl >> 6;           // local head 0/1

    const float* wkc = Wk + (size_t)(ec * 128) * DE + tg;  // coalesced across tl
    const float* ss  = S2 + hl * 1024 + ec * 128;
    float acc = 0.f;
#pragma unroll 8
    for (int i = 0; i < 128; i++)
        acc += wkc[(size_t)i * DE] * ss[i];
    part[t] = acc;
    __syncthreads();

    if (t < 128) {
        float s = 0.f;
#pragma unroll
        for (int e8 = 0; e8 < 8; e8++) s += part[e8 * 128 + t];
        int tg2 = seg * 128 + t;
        s += bk[tg2] * g_V1[b * 16 + (tg2 >> 6)];
        g_ktv[b * DE + tg2] = s;
    }
}

// ------------------------------------------------------- KD: g and c
// grid 128, 256 threads. Wq read exactly once, coalesced. ktv for all 8
// batches cached in registers; 16-lane shuffle reduction per (b, e).
__global__ void __launch_bounds__(256)
k_g(const float* __restrict__ Wq, const float* __restrict__ bq) {
    __shared__ float ks[B_ * DE];     // 32 KB
    const int t = threadIdx.x;
    for (int i = t; i < B_ * DE; i += 256) ks[i] = g_ktv[i];
    __syncthreads();

    float4 ktq[8];
#pragma unroll
    for (int b = 0; b < 8; b++)
        ktq[b] = *(const float4*)&ks[b * DE + t * 4];
    const int h = t >> 4;

#pragma unroll
    for (int r = 0; r < 8; r++) {
        const int e = blockIdx.x * 8 + r;
        float4 w = *(const float4*)&Wq[(size_t)e * DE + t * 4];
        float p[8];
#pragma unroll
        for (int b = 0; b < 8; b++)
            p[b] = w.x * ktq[b].x + w.y * ktq[b].y + w.z * ktq[b].z + w.w * ktq[b].w;
#pragma unroll
        for (int b = 0; b < 8; b++) {
#pragma unroll
            for (int o = 8; o > 0; o >>= 1)
                p[b] += __shfl_down_sync(0xffffffffu, p[b], o, 16);
        }
        if ((t & 15) == 0) {
#pragma unroll
            for (int b = 0; b < 8; b++)
                g_G[((size_t)b * H_ + h) * DE + e] = p[b];
        }
    }

    if (blockIdx.x == 0 && t < 128) {
        int b = t >> 4, h2 = t & 15;
        float c = 0.f;
        for (int d = 0; d < 64; d++)
            c += bq[h2 * 64 + d] * ks[b * DE + h2 * 64 + d];
        g_c[b * 16 + h2] = c;
    }
}

// --------------------------------------------- KE: z = (x.g + c)/8 -> sigmoid
// grid = B*64 (512), 256 threads; thread: (head h, 4 rows). mask is int32.
__global__ void __launch_bounds__(256, 3)
k_out(const float* __restrict__ x, const int* __restrict__ mask,
      float* __restrict__ out) {
    extern __shared__ float sh[];
    float* gs  = sh;              // [16][1026]
    float* c_s = sh + 16 * 1026;  // [16]

    const int b   = blockIdx.x >> 6;
    const int lt  = blockIdx.x & 63;
    const int l0  = lt * 64;
    const int tid = threadIdx.x;

    for (int idx = tid; idx < H_ * DE; idx += 256) {
        int hh = idx >> 10, e = idx & 1023;
        gs[hh * 1026 + e] = g_G[(size_t)b * H_ * DE + idx];
    }
    if (tid < 16) c_s[tid] = g_c[b * 16 + tid];
    __syncthreads();

    const int h  = tid & 15;
    const int lg = tid >> 4;
    const int rbase = l0 + lg * 4;
    const ulonglong2* xr0 = (const ulonglong2*)(x + ((size_t)b * L_ + rbase + 0) * DE);
    const ulonglong2* xr1 = (const ulonglong2*)(x + ((size_t)b * L_ + rbase + 1) * DE);
    const ulonglong2* xr2 = (const ulonglong2*)(x + ((size_t)b * L_ + rbase + 2) * DE);
    const ulonglong2* xr3 = (const ulonglong2*)(x + ((size_t)b * L_ + rbase + 3) * DE);
    const u64* wp  = (const u64*)(gs + h * 1026);

    u64 a0 = 0, a1 = 0, a2 = 0, a3 = 0;
#pragma unroll 4
    for (int e4 = 0; e4 < DE / 4; e4++) {
        u64 w0 = wp[2 * e4], w1 = wp[2 * e4 + 1];
        ulonglong2 p0 = xr0[e4], p1 = xr1[e4], p2 = xr2[e4], p3 = xr3[e4];
        ffma2(a0, p0.x, w0); ffma2(a0, p0.y, w1);
        ffma2(a1, p1.x, w0); ffma2(a1, p1.y, w1);
        ffma2(a2, p2.x, w0); ffma2(a2, p2.y, w1);
        ffma2(a3, p3.x, w0); ffma2(a3, p3.y, w1);
    }
    const float ch = c_s[h];
    u64 acc[4] = {a0, a1, a2, a3};
#pragma unroll
    for (int j = 0; j < 4; j++) {
        float2 f = unpack2(acc[j]);
        float z = (f.x + f.y + ch) * 0.125f;
        float p = 1.f / (1.f + expf(-z));
        int l = rbase + j;
        out[((size_t)b * H_ + h) * L_ + l] = (mask[b * L_ + l] != 0) ? p : 0.f;
    }
}

// --------------------------------------------------------------- launch
extern "C" void kernel_launch(void* const* d_in, const int* in_sizes, int n_in,
                              void* d_out, int out_size) {
    const float* x  = (const float*)d_in[0];
    const int*   mk = (const int*)d_in[1];     // bool mask delivered as int32
    const float* Wq = (const float*)d_in[2];
    const float* bq = (const float*)d_in[3];
    const float* Wk = (const float*)d_in[4];
    const float* bk = (const float*)d_in[5];
    const float* Wv = (const float*)d_in[6];
    const float* bv = (const float*)d_in[7];
    float* out      = (float*)d_out;

    const int smemA = 16 * 1026 * 4 + 16 * 64 * 8;   // 73856 B
    const int smemE = (16 * 1026 + 16) * 4;          // 65728 B
    cudaFuncSetAttribute(k_vS,  cudaFuncAttributeMaxDynamicSharedMemorySize, smemA);
    cudaFuncSetAttribute(k_out, cudaFuncAttributeMaxDynamicSharedMemorySize, smemE);

    k_zero<<<512, 256>>>();
    k_vS  <<<B_ * NCHUNK, 256, smemA>>>(x, Wv, bv);
    k_ktv <<<64, 1024>>>(Wk, bk);
    k_g   <<<128, 256>>>(Wq, bq);
    k_out <<<B_ * 64, 256, smemE>>>(x, mk, out);
}

// round 14
// speedup vs baseline: 1.9344x; 1.5392x over previous
#include <cuda_runtime.h>
#include <math.h>

#define B_  8
#define L_  4096
#define H_  16
#define DE  1024

// Scratch (static device globals — allowed; no runtime allocation)
__device__ float g_S[B_ * H_ * DE];     // reduced S [b][h][e] (atomic-accumulated)
__device__ float g_ktv[B_ * DE];        // [b][h*64+d]
__device__ float g_V1[B_ * H_];         // sum_l v
__device__ float g_c[B_ * H_];          // bq_h . ktv
__device__ float g_G[B_ * H_ * DE];     // [b][h][e]

typedef unsigned long long u64;

__device__ __forceinline__ void ffma2(u64 &d, u64 a, u64 b) {
    asm("fma.rn.f32x2 %0, %1, %2, %0;" : "+l"(d) : "l"(a), "l"(b));
}
__device__ __forceinline__ u64 pack2(float lo, float hi) {
    union { u64 u; float2 f; } c; c.f.x = lo; c.f.y = hi; return c.u;
}
__device__ __forceinline__ float2 unpack2(u64 v) {
    union { u64 u; float2 f; } c; c.u = v; return c.f;
}

// ---------------------------------------------------------------- K0: zero
__global__ void k_zero() {
    int t = blockIdx.x * blockDim.x + threadIdx.x;   // 512*256 = B*H*DE
    g_S[t] = 0.f;
    if (t < B_ * H_) { g_V1[t] = 0.f; g_c[t] = 0.f; }
}

// --------------------------------------------------- KA: fused v + S
// grid = 256 (b, 128-row chunk), 256 threads = 8 head-pairs x 32 row-groups.
// smem: wvT [16][1026] floats + v_s2 [128][16] u64 (packed (v,v), l-major)
__global__ void __launch_bounds__(256, 2)
k_vS(const float* __restrict__ x, const float* __restrict__ Wv,
     const float* __restrict__ bv) {
    extern __shared__ float sh[];
    float* wvT  = sh;                       // 16*1026 floats
    u64*   v_s2 = (u64*)(sh + 16 * 1026);   // [l][h] packed (v,v)

    const int b     = blockIdx.x >> 5;
    const int chunk = blockIdx.x & 31;
    const int l0    = chunk * 128;
    const int tid   = threadIdx.x;

    // wvT[h][e] = Wv[e*16+h]
    for (int idx = tid; idx < DE * H_; idx += 256) {
        int e = idx >> 4, h = idx & 15;
        wvT[h * 1026 + e] = Wv[idx];
    }
    __syncthreads();

    const int hp = tid & 7;          // head pair
    const int lg = tid >> 3;         // row group 0..31
    const int h0 = hp * 2, h1 = h0 + 1;
    const int rbase = l0 + lg * 4;

    // ---- Phase A: v for 4 rows x 2 heads per thread
    {
        const ulonglong2* xr0 = (const ulonglong2*)(x + ((size_t)b * L_ + rbase + 0) * DE);
        const ulonglong2* xr1 = (const ulonglong2*)(x + ((size_t)b * L_ + rbase + 1) * DE);
        const ulonglong2* xr2 = (const ulonglong2*)(x + ((size_t)b * L_ + rbase + 2) * DE);
        const ulonglong2* xr3 = (const ulonglong2*)(x + ((size_t)b * L_ + rbase + 3) * DE);
        const u64* w0p = (const u64*)(wvT + h0 * 1026);
        const u64* w1p = (const u64*)(wvT + h1 * 1026);
        u64 a00=0,a10=0,a20=0,a30=0, a01=0,a11=0,a21=0,a31=0;
#pragma unroll 4
        for (int e4 = 0; e4 < DE / 4; e4++) {
            u64 wa0 = w0p[2*e4], wa1 = w0p[2*e4+1];
            u64 wb0 = w1p[2*e4], wb1 = w1p[2*e4+1];
            ulonglong2 p0 = xr0[e4], p1 = xr1[e4], p2 = xr2[e4], p3 = xr3[e4];
            ffma2(a00, p0.x, wa0); ffma2(a00, p0.y, wa1);
            ffma2(a10, p1.x, wa0); ffma2(a10, p1.y, wa1);
            ffma2(a20, p2.x, wa0); ffma2(a20, p2.y, wa1);
            ffma2(a30, p3.x, wa0); ffma2(a30, p3.y, wa1);
            ffma2(a01, p0.x, wb0); ffma2(a01, p0.y, wb1);
            ffma2(a11, p1.x, wb0); ffma2(a11, p1.y, wb1);
            ffma2(a21, p2.x, wb0); ffma2(a21, p2.y, wb1);
            ffma2(a31, p3.x, wb0); ffma2(a31, p3.y, wb1);
        }
        const float bv0 = bv[h0], bv1 = bv[h1];
        float2 f;
        float vs0 = 0.f, vs1 = 0.f;
        f = unpack2(a00); { float v = f.x + f.y + bv0; v_s2[(lg*4+0)*16 + h0] = pack2(v,v); vs0 += v; }
        f = unpack2(a10); { float v = f.x + f.y + bv0; v_s2[(lg*4+1)*16 + h0] = pack2(v,v); vs0 += v; }
        f = unpack2(a20); { float v = f.x + f.y + bv0; v_s2[(lg*4+2)*16 + h0] = pack2(v,v); vs0 += v; }
        f = unpack2(a30); { float v = f.x + f.y + bv0; v_s2[(lg*4+3)*16 + h0] = pack2(v,v); vs0 += v; }
        f = unpack2(a01); { float v = f.x + f.y + bv1; v_s2[(lg*4+0)*16 + h1] = pack2(v,v); vs1 += v; }
        f = unpack2(a11); { float v = f.x + f.y + bv1; v_s2[(lg*4+1)*16 + h1] = pack2(v,v); vs1 += v; }
        f = unpack2(a21); { float v = f.x + f.y + bv1; v_s2[(lg*4+2)*16 + h1] = pack2(v,v); vs1 += v; }
        f = unpack2(a31); { float v = f.x + f.y + bv1; v_s2[(lg*4+3)*16 + h1] = pack2(v,v); vs1 += v; }
        // V1: lanes t, t^8, t^16, t^24 share the head pair
        vs0 += __shfl_xor_sync(0xffffffffu, vs0, 8);
        vs0 += __shfl_xor_sync(0xffffffffu, vs0, 16);
        vs1 += __shfl_xor_sync(0xffffffffu, vs1, 8);
        vs1 += __shfl_xor_sync(0xffffffffu, vs1, 16);
        if ((tid & 31) < 8) {
            atomicAdd(&g_V1[b * 16 + h0], vs0);
            atomicAdd(&g_V1[b * 16 + h1], vs1);
        }
    }
    __syncthreads();

    // ---- Phase B: S[h][e0..e0+3] += x[l][e] * v[h][l] over 128 rows
    {
        const int e0 = tid * 4;
        u64 accS[16][2];
#pragma unroll
        for (int i = 0; i < 16; i++) { accS[i][0] = 0ULL; accS[i][1] = 0ULL; }

        const ulonglong2* xp =
            (const ulonglong2*)(x + ((size_t)b * L_ + l0) * DE + e0);
        ulonglong2 x4a = xp[0];
        ulonglong2 x4b = xp[DE / 4];
        for (int l = 0; l < 128; l++) {
            int lp = l + 2 < 128 ? l + 2 : l;
            ulonglong2 nxt = xp[(size_t)lp * (DE / 4)];
            const ulonglong2* vp = (const ulonglong2*)(v_s2 + l * 16);
#pragma unroll
            for (int hh = 0; hh < 8; hh++) {
                ulonglong2 v2 = vp[hh];          // broadcast LDS.128: heads 2hh, 2hh+1
                ffma2(accS[2*hh  ][0], x4a.x, v2.x);
                ffma2(accS[2*hh  ][1], x4a.y, v2.x);
                ffma2(accS[2*hh+1][0], x4a.x, v2.y);
                ffma2(accS[2*hh+1][1], x4a.y, v2.y);
            }
            x4a = x4b; x4b = nxt;
        }

        float* sp = g_S + (size_t)b * H_ * DE;
#pragma unroll
        for (int hh = 0; hh < 16; hh++) {
            float2 lo = unpack2(accS[hh][0]);
            float2 hi = unpack2(accS[hh][1]);
            atomicAdd(sp + hh * DE + e0 + 0, lo.x);
            atomicAdd(sp + hh * DE + e0 + 1, lo.y);
            atomicAdd(sp + hh * DE + e0 + 2, hi.x);
            atomicAdd(sp + hh * DE + e0 + 3, hi.y);
        }
    }
}

// ------------------------------------------------ KC: ktv = Wk^T S + bk*V1; c = bq.ktv
// grid 64 = 8b x 8seg, 1024 threads. 8-way e-split with smem reduction.
__global__ void __launch_bounds__(1024)
k_ktv(const float* __restrict__ Wk, const float* __restrict__ bk,
      const float* __restrict__ bq) {
    __shared__ float S2[2 * 1024];
    __shared__ float part[1024];
    const int b   = blockIdx.x >> 3;
    const int seg = blockIdx.x & 7;
    const int t   = threadIdx.x;

    for (int i = t; i < 2048; i += 1024)
        S2[i] = g_S[((size_t)b * 16 + seg * 2) * 1024 + i];
    __syncthreads();

    const int ec = t >> 7;            // e-chunk 0..7
    const int tl = t & 127;           // local output
    const int tg = seg * 128 + tl;    // global hd index
    const int hl = tl >> 6;           // local head 0/1

    const float* wkc = Wk + (size_t)(ec * 128) * DE + tg;  // coalesced across tl
    const float* ss  = S2 + hl * 1024 + ec * 128;
    float acc = 0.f;
#pragma unroll 8
    for (int i = 0; i < 128; i++)
        acc += wkc[(size_t)i * DE] * ss[i];
    part[t] = acc;
    __syncthreads();

    if (t < 128) {
        float s = 0.f;
#pragma unroll
        for (int e8 = 0; e8 < 8; e8++) s += part[e8 * 128 + t];
        int tg2 = seg * 128 + t;
        int h   = tg2 >> 6;
        s += bk[tg2] * g_V1[b * 16 + h];
        g_ktv[b * DE + tg2] = s;
        // c[b][h] += bq[tg2]*s ; warp (32 consecutive t) shares h
        float cc = bq[tg2] * s;
#pragma unroll
        for (int o = 16; o > 0; o >>= 1)
            cc += __shfl_down_sync(0xffffffffu, cc, o);
        if ((t & 31) == 0) atomicAdd(&g_c[b * 16 + h], cc);
    }
}

// ------------------------------------------------------- KD: G[b,h,e] = Wq[e,h*64:].ktv
// grid 512, 256 threads: thread = (e = blk*2 + t>>7, h = (t&127)>>3, b = t&7).
// 32 independent float4 LDGs (MLP 32), 64 FMA, no smem, no shuffles.
__global__ void __launch_bounds__(256)
k_g(const float* __restrict__ Wq) {
    const int t127 = threadIdx.x & 127;
    const int e = blockIdx.x * 2 + (threadIdx.x >> 7);
    const int h = t127 >> 3;
    const int b = t127 & 7;

    const float4* wp = (const float4*)(Wq + (size_t)e * DE + h * 64);
    const float4* kp = (const float4*)(g_ktv + (size_t)b * DE + h * 64);
    float acc = 0.f;
#pragma unroll
    for (int i = 0; i < 16; i++) {
        float4 w = wp[i], k = kp[i];
        acc += w.x * k.x + w.y * k.y + w.z * k.z + w.w * k.w;
    }
    g_G[((size_t)b * H_ + h) * DE + e] = acc;
}

// --------------------------------------------- KE: z = (x.g + c)/8 -> sigmoid
// grid 256 (b, 128-row chunk), 256 threads = 8 head-pairs x 32 row-groups.
__global__ void __launch_bounds__(256, 2)
k_out(const float* __restrict__ x, const int* __restrict__ mask,
      float* __restrict__ out) {
    extern __shared__ float sh[];
    float* gs  = sh;              // [16][1026]
    float* c_s = sh + 16 * 1026;  // [16]

    const int b   = blockIdx.x >> 5;
    const int lt  = blockIdx.x & 31;
    const int l0  = lt * 128;
    const int tid = threadIdx.x;

    for (int idx = tid; idx < H_ * DE; idx += 256) {
        int hh = idx >> 10, e = idx & 1023;
        gs[hh * 1026 + e] = g_G[(size_t)b * H_ * DE + idx];
    }
    if (tid < 16) c_s[tid] = g_c[b * 16 + tid];
    __syncthreads();

    const int hp = tid & 7;
    const int lg = tid >> 3;
    const int h0 = hp * 2, h1 = h0 + 1;
    const int rbase = l0 + lg * 4;

    const ulonglong2* xr0 = (const ulonglong2*)(x + ((size_t)b * L_ + rbase + 0) * DE);
    const ulonglong2* xr1 = (const ulonglong2*)(x + ((size_t)b * L_ + rbase + 1) * DE);
    const ulonglong2* xr2 = (const ulonglong2*)(x + ((size_t)b * L_ + rbase + 2) * DE);
    const ulonglong2* xr3 = (const ulonglong2*)(x + ((size_t)b * L_ + rbase + 3) * DE);
    const u64* w0p = (const u64*)(gs + h0 * 1026);
    const u64* w1p = (const u64*)(gs + h1 * 1026);

    u64 a00=0,a10=0,a20=0,a30=0, a01=0,a11=0,a21=0,a31=0;
#pragma unroll 4
    for (int e4 = 0; e4 < DE / 4; e4++) {
        u64 wa0 = w0p[2*e4], wa1 = w0p[2*e4+1];
        u64 wb0 = w1p[2*e4], wb1 = w1p[2*e4+1];
        ulonglong2 p0 = xr0[e4], p1 = xr1[e4], p2 = xr2[e4], p3 = xr3[e4];
        ffma2(a00, p0.x, wa0); ffma2(a00, p0.y, wa1);
        ffma2(a10, p1.x, wa0); ffma2(a10, p1.y, wa1);
        ffma2(a20, p2.x, wa0); ffma2(a20, p2.y, wa1);
        ffma2(a30, p3.x, wa0); ffma2(a30, p3.y, wa1);
        ffma2(a01, p0.x, wb0); ffma2(a01, p0.y, wb1);
        ffma2(a11, p1.x, wb0); ffma2(a11, p1.y, wb1);
        ffma2(a21, p2.x, wb0); ffma2(a21, p2.y, wb1);
        ffma2(a31, p3.x, wb0); ffma2(a31, p3.y, wb1);
    }

    const float c0 = c_s[h0], c1 = c_s[h1];
    int m[4];
#pragma unroll
    for (int j = 0; j < 4; j++) m[j] = mask[b * L_ + rbase + j];

    u64 A0[4] = {a00, a10, a20, a30};
    u64 A1[4] = {a01, a11, a21, a31};
#pragma unroll
    for (int j = 0; j < 4; j++) {
        float2 f0 = unpack2(A0[j]);
        float2 f1 = unpack2(A1[j]);
        float z0 = (f0.x + f0.y + c0) * 0.125f;
        float z1 = (f1.x + f1.y + c1) * 0.125f;
        float p0 = 1.f / (1.f + expf(-z0));
        float p1 = 1.f / (1.f + expf(-z1));
        int l = rbase + j;
        out[((size_t)b * H_ + h0) * L_ + l] = m[j] ? p0 : 0.f;
        out[((size_t)b * H_ + h1) * L_ + l] = m[j] ? p1 : 0.f;
    }
}

// --------------------------------------------------------------- launch
extern "C" void kernel_launch(void* const* d_in, const int* in_sizes, int n_in,
                              void* d_out, int out_size) {
    const float* x  = (const float*)d_in[0];
    const int*   mk = (const int*)d_in[1];     // bool mask delivered as int32
    const float* Wq = (const float*)d_in[2];
    const float* bq = (const float*)d_in[3];
    const float* Wk = (const float*)d_in[4];
    const float* bk = (const float*)d_in[5];
    const float* Wv = (const float*)d_in[6];
    const float* bv = (const float*)d_in[7];
    float* out      = (float*)d_out;

    const int smemA = 16 * 1026 * 4 + 128 * 16 * 8;  // 65664 + 16384 = 82048 B
    const int smemE = (16 * 1026 + 16) * 4;          // 65728 B
    cudaFuncSetAttribute(k_vS,  cudaFuncAttributeMaxDynamicSharedMemorySize, smemA);
    cudaFuncSetAttribute(k_out, cudaFuncAttributeMaxDynamicSharedMemorySize, smemE);

    k_zero<<<512, 256>>>();
    k_vS  <<<256, 256, smemA>>>(x, Wv, bv);
    k_ktv <<<64, 1024>>>(Wk, bk, bq);
    k_g   <<<512, 256>>>(Wq);
    k_out <<<256, 256, smemE>>>(x, mk, out);
}

// round 17
// speedup vs baseline: 1.9897x; 1.0286x over previous
#include <cuda_runtime.h>
#include <math.h>

#define B_  8
#define L_  4096
#define H_  16
#define DE  1024

// Scratch (static device globals — allowed; no runtime allocation)
__device__ float g_S[B_ * H_ * DE];     // reduced S [b][h][e] (atomic-accumulated)
__device__ float g_ktv[B_ * DE];        // [b][h*64+d]
__device__ float g_V1[B_ * H_];         // sum_l v
__device__ float g_c[B_ * H_];          // bq_h . ktv
__device__ float g_G[B_ * H_ * DE];     // [b][h][e]

typedef unsigned long long u64;

__device__ __forceinline__ void ffma2(u64 &d, u64 a, u64 b) {
    asm("fma.rn.f32x2 %0, %1, %2, %0;" : "+l"(d) : "l"(a), "l"(b));
}
__device__ __forceinline__ u64 pack2(float lo, float hi) {
    union { u64 u; float2 f; } c; c.f.x = lo; c.f.y = hi; return c.u;
}
__device__ __forceinline__ float2 unpack2(u64 v) {
    union { u64 u; float2 f; } c; c.u = v; return c.f;
}

// ---------------------------------------------------------------- K0: zero
__global__ void k_zero() {
    int t = blockIdx.x * blockDim.x + threadIdx.x;   // 512*256 = B*H*DE
    g_S[t] = 0.f;
    if (t < B_ * H_) { g_V1[t] = 0.f; g_c[t] = 0.f; }
}

// --------------------------------------------------- KA: fused v + S
// grid = 256 (b, 128-row chunk), 256 threads = 8 head-pairs x 32 row-groups.
// smem: wvT [16][1026] floats + v_s2 [128][16] u64 (packed (v,v), l-major)
__global__ void __launch_bounds__(256, 2)
k_vS(const float* __restrict__ x, const float* __restrict__ Wv,
     const float* __restrict__ bv) {
    extern __shared__ float sh[];
    float* wvT  = sh;                       // 16*1026 floats
    u64*   v_s2 = (u64*)(sh + 16 * 1026);   // [l][h] packed (v,v)

    const int b     = blockIdx.x >> 5;
    const int chunk = blockIdx.x & 31;
    const int l0    = chunk * 128;
    const int tid   = threadIdx.x;

    // wvT[h][e] = Wv[e*16+h]
    for (int idx = tid; idx < DE * H_; idx += 256) {
        int e = idx >> 4, h = idx & 15;
        wvT[h * 1026 + e] = Wv[idx];
    }
    __syncthreads();

    const int hp = tid & 7;          // head pair
    const int lg = tid >> 3;         // row group 0..31
    const int h0 = hp * 2, h1 = h0 + 1;
    const int rbase = l0 + lg * 4;

    // ---- Phase A: v for 4 rows x 2 heads per thread
    {
        const ulonglong2* xr0 = (const ulonglong2*)(x + ((size_t)b * L_ + rbase + 0) * DE);
        const ulonglong2* xr1 = (const ulonglong2*)(x + ((size_t)b * L_ + rbase + 1) * DE);
        const ulonglong2* xr2 = (const ulonglong2*)(x + ((size_t)b * L_ + rbase + 2) * DE);
        const ulonglong2* xr3 = (const ulonglong2*)(x + ((size_t)b * L_ + rbase + 3) * DE);
        const u64* w0p = (const u64*)(wvT + h0 * 1026);
        const u64* w1p = (const u64*)(wvT + h1 * 1026);
        u64 a00=0,a10=0,a20=0,a30=0, a01=0,a11=0,a21=0,a31=0;
#pragma unroll 4
        for (int e4 = 0; e4 < DE / 4; e4++) {
            u64 wa0 = w0p[2*e4], wa1 = w0p[2*e4+1];
            u64 wb0 = w1p[2*e4], wb1 = w1p[2*e4+1];
            ulonglong2 p0 = xr0[e4], p1 = xr1[e4], p2 = xr2[e4], p3 = xr3[e4];
            ffma2(a00, p0.x, wa0); ffma2(a00, p0.y, wa1);
            ffma2(a10, p1.x, wa0); ffma2(a10, p1.y, wa1);
            ffma2(a20, p2.x, wa0); ffma2(a20, p2.y, wa1);
            ffma2(a30, p3.x, wa0); ffma2(a30, p3.y, wa1);
            ffma2(a01, p0.x, wb0); ffma2(a01, p0.y, wb1);
            ffma2(a11, p1.x, wb0); ffma2(a11, p1.y, wb1);
            ffma2(a21, p2.x, wb0); ffma2(a21, p2.y, wb1);
            ffma2(a31, p3.x, wb0); ffma2(a31, p3.y, wb1);
        }
        const float bv0 = bv[h0], bv1 = bv[h1];
        float2 f;
        float vs0 = 0.f, vs1 = 0.f;
        f = unpack2(a00); { float v = f.x + f.y + bv0; v_s2[(lg*4+0)*16 + h0] = pack2(v,v); vs0 += v; }
        f = unpack2(a10); { float v = f.x + f.y + bv0; v_s2[(lg*4+1)*16 + h0] = pack2(v,v); vs0 += v; }
        f = unpack2(a20); { float v = f.x + f.y + bv0; v_s2[(lg*4+2)*16 + h0] = pack2(v,v); vs0 += v; }
        f = unpack2(a30); { float v = f.x + f.y + bv0; v_s2[(lg*4+3)*16 + h0] = pack2(v,v); vs0 += v; }
        f = unpack2(a01); { float v = f.x + f.y + bv1; v_s2[(lg*4+0)*16 + h1] = pack2(v,v); vs1 += v; }
        f = unpack2(a11); { float v = f.x + f.y + bv1; v_s2[(lg*4+1)*16 + h1] = pack2(v,v); vs1 += v; }
        f = unpack2(a21); { float v = f.x + f.y + bv1; v_s2[(lg*4+2)*16 + h1] = pack2(v,v); vs1 += v; }
        f = unpack2(a31); { float v = f.x + f.y + bv1; v_s2[(lg*4+3)*16 + h1] = pack2(v,v); vs1 += v; }
        // V1: lanes t, t^8, t^16, t^24 share the head pair
        vs0 += __shfl_xor_sync(0xffffffffu, vs0, 8);
        vs0 += __shfl_xor_sync(0xffffffffu, vs0, 16);
        vs1 += __shfl_xor_sync(0xffffffffu, vs1, 8);
        vs1 += __shfl_xor_sync(0xffffffffu, vs1, 16);
        if ((tid & 31) < 8) {
            atomicAdd(&g_V1[b * 16 + h0], vs0);
            atomicAdd(&g_V1[b * 16 + h1], vs1);
        }
    }
    __syncthreads();

    // ---- Phase B: S[h][e0..e0+3] += x[l][e] * v[h][l] over 128 rows.
    // Depth-4 prefetch ring: ~4x bytes-in-flight vs the old depth-2 scheme
    // to cover the 234-cyc L2 hit latency of the re-read of x.
    {
        const int e0 = tid * 4;
        u64 accS[16][2];
#pragma unroll
        for (int i = 0; i < 16; i++) { accS[i][0] = 0ULL; accS[i][1] = 0ULL; }

        const ulonglong2* xp =
            (const ulonglong2*)(x + ((size_t)b * L_ + l0) * DE + e0);
        ulonglong2 r0 = xp[0];
        ulonglong2 r1 = xp[1 * (DE / 4)];
        ulonglong2 r2 = xp[2 * (DE / 4)];
        ulonglong2 r3 = xp[3 * (DE / 4)];

        for (int lb = 0; lb < 128; lb += 4) {
            int p0i = lb + 4 < 128 ? lb + 4 : 127;
            int p1i = lb + 5 < 128 ? lb + 5 : 127;
            int p2i = lb + 6 < 128 ? lb + 6 : 127;
            int p3i = lb + 7 < 128 ? lb + 7 : 127;
            ulonglong2 n0 = xp[(size_t)p0i * (DE / 4)];
            ulonglong2 n1 = xp[(size_t)p1i * (DE / 4)];
            ulonglong2 n2 = xp[(size_t)p2i * (DE / 4)];
            ulonglong2 n3 = xp[(size_t)p3i * (DE / 4)];

#pragma unroll
            for (int k = 0; k < 4; k++) {
                ulonglong2 xv = (k == 0) ? r0 : (k == 1) ? r1 : (k == 2) ? r2 : r3;
                const ulonglong2* vp = (const ulonglong2*)(v_s2 + (lb + k) * 16);
#pragma unroll
                for (int hh = 0; hh < 8; hh++) {
                    ulonglong2 v2 = vp[hh];      // broadcast LDS.128: heads 2hh, 2hh+1
                    ffma2(accS[2*hh  ][0], xv.x, v2.x);
                    ffma2(accS[2*hh  ][1], xv.y, v2.x);
                    ffma2(accS[2*hh+1][0], xv.x, v2.y);
                    ffma2(accS[2*hh+1][1], xv.y, v2.y);
                }
            }
            r0 = n0; r1 = n1; r2 = n2; r3 = n3;
        }

        float* sp = g_S + (size_t)b * H_ * DE;
#pragma unroll
        for (int hh = 0; hh < 16; hh++) {
            float2 lo = unpack2(accS[hh][0]);
            float2 hi = unpack2(accS[hh][1]);
            atomicAdd(sp + hh * DE + e0 + 0, lo.x);
            atomicAdd(sp + hh * DE + e0 + 1, lo.y);
            atomicAdd(sp + hh * DE + e0 + 2, hi.x);
            atomicAdd(sp + hh * DE + e0 + 3, hi.y);
        }
    }
}

// ------------------------------------------------ KC: ktv = Wk^T S + bk*V1; c = bq.ktv
// grid 64 = 8b x 8seg, 1024 threads. 8-way e-split with smem reduction.
__global__ void __launch_bounds__(1024)
k_ktv(const float* __restrict__ Wk, const float* __restrict__ bk,
      const float* __restrict__ bq) {
    __shared__ float S2[2 * 1024];
    __shared__ float part[1024];
    const int b   = blockIdx.x >> 3;
    const int seg = blockIdx.x & 7;
    const int t   = threadIdx.x;

    for (int i = t; i < 2048; i += 1024)
        S2[i] = g_S[((size_t)b * 16 + seg * 2) * 1024 + i];
    __syncthreads();

    const int ec = t >> 7;            // e-chunk 0..7
    const int tl = t & 127;           // local output
    const int tg = seg * 128 + tl;    // global hd index
    const int hl = tl >> 6;           // local head 0/1

    const float* wkc = Wk + (size_t)(ec * 128) * DE + tg;  // coalesced across tl
    const float* ss  = S2 + hl * 1024 + ec * 128;
    float acc = 0.f;
#pragma unroll 8
    for (int i = 0; i < 128; i++)
        acc += wkc[(size_t)i * DE] * ss[i];
    part[t] = acc;
    __syncthreads();

    if (t < 128) {
        float s = 0.f;
#pragma unroll
        for (int e8 = 0; e8 < 8; e8++) s += part[e8 * 128 + t];
        int tg2 = seg * 128 + t;
        int h   = tg2 >> 6;
        s += bk[tg2] * g_V1[b * 16 + h];
        g_ktv[b * DE + tg2] = s;
        // c[b][h] += bq[tg2]*s ; warp (32 consecutive t) shares h
        float cc = bq[tg2] * s;
#pragma unroll
        for (int o = 16; o > 0; o >>= 1)
            cc += __shfl_down_sync(0xffffffffu, cc, o);
        if ((t & 31) == 0) atomicAdd(&g_c[b * 16 + h], cc);
    }
}

// ------------------------------------------------------- KD: G[b,h,e] = Wq[e,h*64:].ktv
// grid 512, 256 threads: thread = (e = blk*2 + t>>7, h = (t&127)>>3, b = t&7).
// ktv staged in smem, padded stride 1028 -> conflict-free LDS.128 across the
// 8 b-lanes (4b mod 32 distinct). This removes the 16-line-per-warp L1 scatter
// that bound the previous version (L1=55%, 300 GB/s).
__global__ void __launch_bounds__(256)
k_g(const float* __restrict__ Wq) {
    __shared__ float ks[8 * 1028];    // 32896 B
    const int tid = threadIdx.x;
    for (int i = tid; i < B_ * DE; i += 256) {
        int b = i >> 10, d = i & 1023;
        ks[b * 1028 + d] = g_ktv[i];
    }
    __syncthreads();

    const int t127 = tid & 127;
    const int e = blockIdx.x * 2 + (tid >> 7);
    const int h = t127 >> 3;
    const int b = t127 & 7;

    const float4* wp = (const float4*)(Wq + (size_t)e * DE + h * 64);
    const float4* kp = (const float4*)(ks + b * 1028 + h * 64);
    float acc = 0.f;
#pragma unroll
    for (int i = 0; i < 16; i++) {
        float4 w = wp[i], k = kp[i];
        acc += w.x * k.x + w.y * k.y + w.z * k.z + w.w * k.w;
    }
    g_G[((size_t)b * H_ + h) * DE + e] = acc;
}

// --------------------------------------------- KE: z = (x.g + c)/8 -> sigmoid
// grid 256 (b, 128-row chunk), 256 threads = 8 head-pairs x 32 row-groups.
// Results staged in a smem p-tile and written back coalesced (the direct
// h-strided STG.32 pattern produced 32-sector store wavefronts).
__global__ void __launch_bounds__(256, 2)
k_out(const float* __restrict__ x, const int* __restrict__ mask,
      float* __restrict__ out) {
    extern __shared__ float sh[];
    float* gs  = sh;                       // [16][1026]
    float* c_s = sh + 16 * 1026;           // [16]
    float* p_s = sh + 16 * 1026 + 16;      // [16][132] p-tile, 16B-aligned rows

    const int b   = blockIdx.x >> 5;
    const int lt  = blockIdx.x & 31;
    const int l0  = lt * 128;
    const int tid = threadIdx.x;

    for (int idx = tid; idx < H_ * DE; idx += 256) {
        int hh = idx >> 10, e = idx & 1023;
        gs[hh * 1026 + e] = g_G[(size_t)b * H_ * DE + idx];
    }
    if (tid < 16) c_s[tid] = g_c[b * 16 + tid];
    __syncthreads();

    const int hp = tid & 7;
    const int lg = tid >> 3;
    const int h0 = hp * 2, h1 = h0 + 1;
    const int rbase = l0 + lg * 4;

    const ulonglong2* xr0 = (const ulonglong2*)(x + ((size_t)b * L_ + rbase + 0) * DE);
    const ulonglong2* xr1 = (const ulonglong2*)(x + ((size_t)b * L_ + rbase + 1) * DE);
    const ulonglong2* xr2 = (const ulonglong2*)(x + ((size_t)b * L_ + rbase + 2) * DE);
    const ulonglong2* xr3 = (const ulonglong2*)(x + ((size_t)b * L_ + rbase + 3) * DE);
    const u64* w0p = (const u64*)(gs + h0 * 1026);
    const u64* w1p = (const u64*)(gs + h1 * 1026);

    u64 a00=0,a10=0,a20=0,a30=0, a01=0,a11=0,a21=0,a31=0;
#pragma unroll 4
    for (int e4 = 0; e4 < DE / 4; e4++) {
        u64 wa0 = w0p[2*e4], wa1 = w0p[2*e4+1];
        u64 wb0 = w1p[2*e4], wb1 = w1p[2*e4+1];
        ulonglong2 p0 = xr0[e4], p1 = xr1[e4], p2 = xr2[e4], p3 = xr3[e4];
        ffma2(a00, p0.x, wa0); ffma2(a00, p0.y, wa1);
        ffma2(a10, p1.x, wa0); ffma2(a10, p1.y, wa1);
        ffma2(a20, p2.x, wa0); ffma2(a20, p2.y, wa1);
        ffma2(a30, p3.x, wa0); ffma2(a30, p3.y, wa1);
        ffma2(a01, p0.x, wb0); ffma2(a01, p0.y, wb1);
        ffma2(a11, p1.x, wb0); ffma2(a11, p1.y, wb1);
        ffma2(a21, p2.x, wb0); ffma2(a21, p2.y, wb1);
        ffma2(a31, p3.x, wb0); ffma2(a31, p3.y, wb1);
    }

    const float c0 = c_s[h0], c1 = c_s[h1];
    int m[4];
#pragma unroll
    for (int j = 0; j < 4; j++) m[j] = mask[b * L_ + rbase + j];

    u64 A0[4] = {a00, a10, a20, a30};
    u64 A1[4] = {a01, a11, a21, a31};
#pragma unroll
    for (int j = 0; j < 4; j++) {
        float2 f0 = unpack2(A0[j]);
        float2 f1 = unpack2(A1[j]);
        float z0 = (f0.x + f0.y + c0) * 0.125f;
        float z1 = (f1.x + f1.y + c1) * 0.125f;
        float p0 = 1.f / (1.f + expf(-z0));
        float p1 = 1.f / (1.f + expf(-z1));
        int lrel = lg * 4 + j;
        p_s[h0 * 132 + lrel] = m[j] ? p0 : 0.f;
        p_s[h1 * 132 + lrel] = m[j] ? p1 : 0.f;
    }
    __syncthreads();

    // Coalesced write-back: thread = (h2 = tid>>4, 8 l's)
    const int h2 = tid >> 4;
    const int lr = (tid & 15) * 8;
    float4 q0 = *(const float4*)&p_s[h2 * 132 + lr];
    float4 q1 = *(const float4*)&p_s[h2 * 132 + lr + 4];
    float4* op = (float4*)(out + ((size_t)b * H_ + h2) * L_ + l0 + lr);
    op[0] = q0;
    op[1] = q1;
}

// --------------------------------------------------------------- launch
extern "C" void kernel_launch(void* const* d_in, const int* in_sizes, int n_in,
                              void* d_out, int out_size) {
    const float* x  = (const float*)d_in[0];
    const int*   mk = (const int*)d_in[1];     // bool mask delivered as int32
    const float* Wq = (const float*)d_in[2];
    const float* bq = (const float*)d_in[3];
    const float* Wk = (const float*)d_in[4];
    const float* bk = (const float*)d_in[5];
    const float* Wv = (const float*)d_in[6];
    const float* bv = (const float*)d_in[7];
    float* out      = (float*)d_out;

    const int smemA = 16 * 1026 * 4 + 128 * 16 * 8;          // 82048 B
    const int smemE = (16 * 1026 + 16 + 16 * 132) * 4;       // 74176 B
    cudaFuncSetAttribute(k_vS,  cudaFuncAttributeMaxDynamicSharedMemorySize, smemA);
    cudaFuncSetAttribute(k_out, cudaFuncAttributeMaxDynamicSharedMemorySize, smemE);

    k_zero<<<512, 256>>>();
    k_vS  <<<256, 256, smemA>>>(x, Wv, bv);
    k_ktv <<<64, 1024>>>(Wk, bk, bq);
    k_g   <<<512, 256>>>(Wq);
    k_out <<<256, 256, smemE>>>(x, mk, out);
}